// round 13
// baseline (speedup 1.0000x reference)
#include <cuda_runtime.h>
#include <cuda_fp16.h>
#include <math.h>
#include <cstdint>
#include <cstddef>

typedef __half fp16;

#define MROWS 32768
#define HD    512
#define WSZ   (512*512)
#define WELEMS  ((size_t)WSZ)

#define BM 128
#define BN 256
#define NTH 256

// smem: 1024 B header (bias, 256 floats) + 5 stages x 24 KB (A 8K + W 16K)
#define A_OFF  0u
#define W_OFF  8192u
#define STAGE  24576u
#define NSTAGE 5
#define SMEMB  (1024u + NSTAGE*STAGE)   // 123904

// ------------- scratch (static device arrays, no runtime alloc) -------------
__device__ fp16  g_X [(size_t)MROWS * HD];
__device__ fp16  g_H0[(size_t)MROWS * HD];
__device__ fp16  g_H1[(size_t)MROWS * HD];
__device__ fp16  g_W [4 * WELEMS];
__device__ float g_beff[2 * HD];

// ----------------------------- PTX helpers ----------------------------------
__device__ __forceinline__ uint32_t s2u(const void* p) {
    uint32_t a;
    asm("{ .reg .u64 t; cvta.to.shared.u64 t, %1; cvt.u32.u64 %0, t; }" : "=r"(a) : "l"(p));
    return a;
}
__device__ __forceinline__ void cp16(uint32_t dst, const void* src) {
    asm volatile("cp.async.cg.shared.global [%0], [%1], 16;" :: "r"(dst), "l"(src));
}
#define CP_COMMIT() asm volatile("cp.async.commit_group;" ::: "memory")
#define CP_WAIT(n)  asm volatile("cp.async.wait_group %0;" :: "n"(n) : "memory")

__device__ __forceinline__ void ldsm4(uint32_t& r0, uint32_t& r1, uint32_t& r2,
                                      uint32_t& r3, uint32_t addr) {
    asm volatile("ldmatrix.sync.aligned.m8n8.x4.shared.b16 {%0,%1,%2,%3}, [%4];"
                 : "=r"(r0), "=r"(r1), "=r"(r2), "=r"(r3) : "r"(addr));
}
__device__ __forceinline__ void mma16816(float* c, const uint32_t* a, const uint32_t* b) {
    asm volatile(
        "mma.sync.aligned.m16n8k16.row.col.f32.f16.f16.f32 "
        "{%0,%1,%2,%3}, {%4,%5,%6,%7}, {%8,%9}, {%0,%1,%2,%3};"
        : "+f"(c[0]), "+f"(c[1]), "+f"(c[2]), "+f"(c[3])
        : "r"(a[0]), "r"(a[1]), "r"(a[2]), "r"(a[3]), "r"(b[0]), "r"(b[1]));
}

// fast accurate tanh: 1 - 2/(exp(2x)+1)
__device__ __forceinline__ float tfast(float x) {
    float e, r;
    asm("ex2.approx.f32 %0, %1;" : "=f"(e) : "f"(x * 2.8853900817779268f));
    asm("rcp.approx.f32 %0, %1;" : "=f"(r) : "f"(e + 1.0f));
    return fmaf(-2.0f, r, 1.0f);
}

// ---------------------------- GEMM stage kernel -----------------------------
// acc[m][n] = sum_k A[m][k]*W[n][k] + bias, opt tanh.
// A, W: single fp16 planes, row stride 512. fp32 accumulation.
// Warp tile 64x64 (2x4 warp grid over BM=128 x BN=256).
template<bool DO_TANH, bool HSF, bool TRANS>
__global__ void __launch_bounds__(NTH, 1) gemm_stage(
    const fp16* __restrict__ A0, const fp16* __restrict__ W0,
    const float* __restrict__ bias0, const float* __restrict__ bias1,
    fp16* __restrict__ outA, float* __restrict__ outF, float* __restrict__ hsf)
{
    extern __shared__ char smem[];
    const uint32_t sb = s2u(smem);
    const int t   = threadIdx.x;
    const int wid = t >> 5;
    const int lid = t & 31;
    const int n0  = blockIdx.x * BN;
    const int m0  = blockIdx.y * BM;
    const int wm  = wid >> 2;      // 0..1 (M, 64 rows)
    const int wn  = wid & 3;       // 0..3 (N, 64 cols)

    if (t < BN) {
        float b = bias0[n0 + t];
        if (bias1) b += bias1[n0 + t];
        ((float*)smem)[t] = b;
    }

    float acc[4][8][4];
#pragma unroll
    for (int mt = 0; mt < 4; ++mt)
#pragma unroll
        for (int nt = 0; nt < 8; ++nt)
#pragma unroll
            for (int e = 0; e < 4; ++e) acc[mt][nt][e] = 0.0f;

    // ldmatrix per-lane addressing (64 B rows: 4 chunk16 columns, swizzle key r&3)
    const int q   = lid >> 3;        // quadrant 0..3
    const int lr8 = lid & 7;
    const int sws = lr8 & 3;
    const uint32_t aOff = (uint32_t)((wm * 64 + (q & 1) * 8 + lr8) * 64);
    const int aHalf = q >> 1;
    const uint32_t bOff = (uint32_t)((wn * 64 + (q >> 1) * 8 + lr8) * 64);
    const int bHalf = q & 1;

    const int NC = 16;   // KC=32 chunks over K=512

    auto load_chunk = [&](int cc) {
        const int kc = cc;
        const uint32_t st = sb + 1024 + (uint32_t)(cc % NSTAGE) * STAGE;
#pragma unroll
        for (int i = 0; i < 2; ++i) {                 // A: 128 rows x 4 c16
            int idx = t + i * NTH;
            int r = idx >> 2, c = idx & 3;
            uint32_t d = st + A_OFF + r * 64 + (uint32_t)((c ^ (r & 3)) << 4);
            cp16(d, A0 + (size_t)(m0 + r) * HD + kc * 32 + c * 8);
        }
#pragma unroll
        for (int i = 0; i < 4; ++i) {                 // W: 256 rows x 4 c16
            int idx = t + i * NTH;
            int r = idx >> 2, c = idx & 3;
            uint32_t d = st + W_OFF + r * 64 + (uint32_t)((c ^ (r & 3)) << 4);
            cp16(d, W0 + (size_t)(n0 + r) * HD + kc * 32 + c * 8);
        }
        CP_COMMIT();
    };

    load_chunk(0);
    load_chunk(1);
    load_chunk(2);
    load_chunk(3);

#pragma unroll 1
    for (int cc = 0; cc < NC; ++cc) {
        // wait until chunk cc's group is complete
        const int rem = NC - 1 - cc;   // groups issued after cc
        if      (rem >= 3) CP_WAIT(3);
        else if (rem == 2) CP_WAIT(2);
        else if (rem == 1) CP_WAIT(1);
        else               CP_WAIT(0);
        __syncthreads();
        if (cc + 4 < NC) load_chunk(cc + 4);

        const uint32_t st = sb + 1024 + (uint32_t)(cc % NSTAGE) * STAGE;
        const uint32_t aB = st + A_OFF + aOff;
        const uint32_t bB = st + W_OFF + bOff;

#pragma unroll
        for (int ks = 0; ks < 2; ++ks) {
            const uint32_t ca = (uint32_t)(((2 * ks + aHalf) ^ sws) << 4);
            const uint32_t cb = (uint32_t)(((2 * ks + bHalf) ^ sws) << 4);
            uint32_t a[4][4], b[8][2];

#pragma unroll
            for (int bt = 0; bt < 4; ++bt)
                ldsm4(b[2*bt][0], b[2*bt][1], b[2*bt+1][0], b[2*bt+1][1],
                      bB + bt * 1024 + cb);
#pragma unroll
            for (int mt = 0; mt < 4; ++mt)
                ldsm4(a[mt][0], a[mt][1], a[mt][2], a[mt][3],
                      aB + mt * 1024 + ca);
#pragma unroll
            for (int mt = 0; mt < 4; ++mt)
#pragma unroll
                for (int nt = 0; nt < 8; ++nt)
                    mma16816(acc[mt][nt], a[mt], b[nt]);
        }
        __syncthreads();
    }

    // ------------------------------ epilogue --------------------------------
    const float* bsm = (const float*)smem;
    const int lq = lid >> 2;
    const int lr = lid & 3;

#pragma unroll
    for (int mt = 0; mt < 4; ++mt) {
#pragma unroll
        for (int hf = 0; hf < 2; ++hf) {
            const int m = m0 + wm * 64 + mt * 16 + lq + hf * 8;
#pragma unroll
            for (int nt = 0; nt < 8; ++nt) {
                const int n = n0 + wn * 64 + nt * 8 + lr * 2;
                float x0 = acc[mt][nt][hf * 2 + 0] + bsm[n - n0];
                float x1 = acc[mt][nt][hf * 2 + 1] + bsm[n - n0 + 1];
                if (DO_TANH) { x0 = tfast(x0); x1 = tfast(x1); }

                if (TRANS) {
                    const int s = m & 4095, bb = m >> 12;
                    float* dst = outF + ((size_t)(s * 8 + bb)) * HD + n;
                    *(float2*)dst = make_float2(x0, x1);
                } else {
                    __half2 hh;
                    hh.x = __float2half_rn(x0);
                    hh.y = __float2half_rn(x1);
                    *(__half2*)(outA + (size_t)m * HD + n) = hh;
                }
                if (HSF && ((m & 4095) == 4095)) {
                    float* hd = hsf + (size_t)(m >> 12) * HD + n;
                    *(float2*)hd = make_float2(x0, x1);
                }
            }
        }
    }
}

// --------------------------- fused prep kernel -------------------------------
//   blocks [0,128)      : Weff = Whh + Wxh@Why -> fp16 plane (slots 1,2)
//   blocks [128,256)    : beff = bhh + bxh + Wxh@bhy (warp reductions)
//   blocks [256,2304)   : convert X -> g_X (fp16)
//   blocks [2304,2368)  : convert W_xh0 / final projection -> fp16 (slots 0,3)
struct PrepP {
    const float* Wxh[2];
    const float* Why[2];
    const float* Whh[2];
    fp16*        WeffC[2];
    const float* bhh[2];
    const float* bxh[2];
    const float* bhy[2];
    float*       beff[2];
    const float* xs;
    fp16*        X;
    const float* Wraw[2];
    fp16*        Wbase;
};

__device__ void prep_weff(const PrepP& p, int id, int t)
{
    const int l  = id >> 6;
    const int rm = id & 63;
    const int m0 = (rm >> 3) * 64;
    const int n0 = (rm & 7) * 64;
    const float* __restrict__ A = p.Wxh[l];
    const float* __restrict__ B = p.Why[l];
    const float* __restrict__ Wadd = p.Whh[l];
    fp16* __restrict__ C = p.WeffC[l];

    __shared__ float As[16][64];
    __shared__ float Bs[16][64];
    const int tx = t & 15, ty = t >> 4;

    float acc[4][4] = {};
#pragma unroll 1
    for (int kt = 0; kt < 512; kt += 16) {
#pragma unroll
        for (int e = t; e < 1024; e += 256) {
            int am = e >> 4, ak = e & 15;
            As[ak][am] = A[(size_t)(m0 + am) * 512 + kt + ak];
            int bj = e & 63, bk = e >> 6;
            Bs[bk][bj] = B[(size_t)(kt + bk) * 512 + n0 + bj];
        }
        __syncthreads();
#pragma unroll
        for (int k = 0; k < 16; ++k) {
            float af[4], bf[4];
#pragma unroll
            for (int i = 0; i < 4; ++i) af[i] = As[k][ty * 4 + i];
#pragma unroll
            for (int j = 0; j < 4; ++j) bf[j] = Bs[k][tx * 4 + j];
#pragma unroll
            for (int i = 0; i < 4; ++i)
#pragma unroll
                for (int j = 0; j < 4; ++j)
                    acc[i][j] = fmaf(af[i], bf[j], acc[i][j]);
        }
        __syncthreads();
    }

    const int kcol = n0 + tx * 4;
#pragma unroll
    for (int i = 0; i < 4; ++i) {
        const int n = m0 + ty * 4 + i;
        fp16 h4[4];
#pragma unroll
        for (int j = 0; j < 4; ++j)
            h4[j] = __float2half_rn(Wadd[(size_t)n * 512 + kcol + j] + acc[i][j]);
        *(uint2*)(C + (size_t)n * 512 + kcol) = *(uint2*)h4;
    }
}

__device__ void prep_beff(const PrepP& p, int id, int t)
{
    const int gw = id * 8 + (t >> 5);
    const int l = gw >> 9;
    const int n = gw & 511;
    const int lane = t & 31;
    const float* W  = p.Wxh[l] + (size_t)n * 512 + lane * 16;
    const float* bh = p.bhy[l] + lane * 16;
    float s = 0.0f;
#pragma unroll
    for (int k = 0; k < 16; k += 4) {
        float4 w = *(const float4*)(W + k);
        float4 b = *(const float4*)(bh + k);
        s = fmaf(w.x, b.x, s); s = fmaf(w.y, b.y, s);
        s = fmaf(w.z, b.z, s); s = fmaf(w.w, b.w, s);
    }
#pragma unroll
    for (int o = 16; o; o >>= 1) s += __shfl_xor_sync(0xFFFFFFFFu, s, o);
    if (lane == 0) p.beff[l][n] = p.bhh[l][n] + p.bxh[l][n] + s;
}

__device__ void prep_cvt(const float* __restrict__ src0, fp16* __restrict__ d)
{
    uint32_t h[16];
#pragma unroll
    for (int j = 0; j < 8; ++j) {
        float4 v = *(const float4*)(src0 + j * 4);
        __half2 h0, h1;
        h0.x = __float2half_rn(v.x); h0.y = __float2half_rn(v.y);
        h1.x = __float2half_rn(v.z); h1.y = __float2half_rn(v.w);
        h[2*j] = *(uint32_t*)&h0; h[2*j+1] = *(uint32_t*)&h1;
    }
#pragma unroll
    for (int j = 0; j < 4; ++j)
        ((uint4*)d)[j] = *(uint4*)(h + 4*j);
}

__global__ void __launch_bounds__(256) k_prep(PrepP p)
{
    const int bid = blockIdx.x;
    const int t   = threadIdx.x;

    if (bid < 128) {
        prep_weff(p, bid, t);
    } else if (bid < 256) {
        prep_beff(p, bid - 128, t);
    } else if (bid < 2304) {
        const size_t off = ((size_t)(bid - 256) * 256 + t) * 32;
        prep_cvt(p.xs + off, p.X + off);
    } else {
        const size_t idx = (size_t)(bid - 2304) * 256 + t;
        const int slot = (int)(idx >> 13);           // 0 or 1
        const size_t off = (idx & 8191) * 32;
        prep_cvt(p.Wraw[slot] + off,
                 p.Wbase + (size_t)(slot * 3) * WELEMS + off);
    }
}

// --------------------------------- launcher ---------------------------------
extern "C" void kernel_launch(void* const* d_in, const int* in_sizes, int n_in,
                              void* d_out, int out_size)
{
    const float* xs     = (const float*)d_in[0];
    const float* W_xh0  = (const float*)d_in[1];
    const float* b_xh0  = (const float*)d_in[2];
    const float* b_hh0  = (const float*)d_in[4];
    const float* W_hy0  = (const float*)d_in[5];
    const float* b_hy0  = (const float*)d_in[6];
    const float* W_xh_h = (const float*)d_in[7];
    const float* b_xh_h = (const float*)d_in[8];
    const float* W_hh_h = (const float*)d_in[9];
    const float* b_hh_h = (const float*)d_in[10];
    const float* W_hy_h = (const float*)d_in[11];
    const float* b_hy_h = (const float*)d_in[12];

    float* out = (float*)d_out;
    float* hs_final = out + (size_t)4096 * 8 * HD;

    fp16 *X, *H0, *H1, *Wb;
    float *beff;
    cudaGetSymbolAddress((void**)&X,   g_X);
    cudaGetSymbolAddress((void**)&H0,  g_H0);
    cudaGetSymbolAddress((void**)&H1,  g_H1);
    cudaGetSymbolAddress((void**)&Wb,  g_W);
    cudaGetSymbolAddress((void**)&beff, g_beff);

    cudaFuncSetAttribute(gemm_stage<true,  false, false>,
                         cudaFuncAttributeMaxDynamicSharedMemorySize, SMEMB);
    cudaFuncSetAttribute(gemm_stage<true,  true,  false>,
                         cudaFuncAttributeMaxDynamicSharedMemorySize, SMEMB);
    cudaFuncSetAttribute(gemm_stage<false, false, true >,
                         cudaFuncAttributeMaxDynamicSharedMemorySize, SMEMB);

#define WS(s) (Wb + (size_t)(s) * WELEMS)

    // ---- fused prep ----
    PrepP pp;
    pp.Wxh[0] = W_xh_h;      pp.Wxh[1] = W_xh_h + WSZ;
    pp.Why[0] = W_hy0;       pp.Why[1] = W_hy_h;
    pp.Whh[0] = W_hh_h;      pp.Whh[1] = W_hh_h + WSZ;
    pp.WeffC[0] = WS(1);     pp.WeffC[1] = WS(2);
    pp.bhh[0] = b_hh_h;      pp.bhh[1] = b_hh_h + HD;
    pp.bxh[0] = b_xh_h;      pp.bxh[1] = b_xh_h + HD;
    pp.bhy[0] = b_hy0;       pp.bhy[1] = b_hy_h;
    pp.beff[0] = beff;       pp.beff[1] = beff + HD;
    pp.xs = xs;
    pp.X  = X;
    pp.Wraw[0] = W_xh0;
    pp.Wraw[1] = W_hy_h + WSZ;
    pp.Wbase = Wb;
    k_prep<<<2368, 256>>>(pp);

    dim3 grid(HD / BN, MROWS / BM);   // (2, 256) = 512 CTAs
    dim3 block(NTH);

    // 1) h0 = tanh(X @ W_xh0^T + b_xh0 + b_hh0)
    gemm_stage<true, false, false><<<grid, block, SMEMB>>>(
        X, WS(0), b_xh0, b_hh0, H0, nullptr, nullptr);
    // 2) h1 = tanh(h0 @ Weff0^T + beff0)
    gemm_stage<true, false, false><<<grid, block, SMEMB>>>(
        H0, WS(1), beff, nullptr, H1, nullptr, nullptr);
    // 3) h2 = tanh(h1 @ Weff1^T + beff1)  (+ hs_final)
    gemm_stage<true, true, false><<<grid, block, SMEMB>>>(
        H1, WS(2), beff + HD, nullptr, H0, nullptr, hs_final);
    // 4) outputs = (h2 @ W_hy_h[1]^T + b_hy_h[1]) -> [S, B, H] fp32
    gemm_stage<false, false, true><<<grid, block, SMEMB>>>(
        H0, WS(3), b_hy_h + HD, nullptr, nullptr, out, nullptr);
#undef WS
}

// round 14
// speedup vs baseline: 1.4789x; 1.4789x over previous
#include <cuda_runtime.h>
#include <cuda_fp16.h>
#include <math.h>
#include <cstdint>
#include <cstddef>

typedef __half fp16;

#define MROWS 32768
#define HD    512
#define WSZ   (512*512)
#define WELEMS  ((size_t)WSZ)

#define BM 128
#define BN 128
#define NTH 256

// smem: 1024 B header (bias) + 3 stages x 32 KB (A 16K + W 16K, KC=64)
#define A_OFF  0u
#define W_OFF  16384u
#define STAGE  32768u
#define NSTAGE 3
#define SMEMB  (1024u + NSTAGE*STAGE)   // 99328

// ------------- scratch (static device arrays, no runtime alloc) -------------
__device__ fp16  g_X [(size_t)MROWS * HD];
__device__ fp16  g_H0[(size_t)MROWS * HD];
__device__ fp16  g_H1[(size_t)MROWS * HD];
__device__ fp16  g_W [4 * WELEMS];
__device__ float g_beff[2 * HD];

// ----------------------------- PTX helpers ----------------------------------
__device__ __forceinline__ uint32_t s2u(const void* p) {
    uint32_t a;
    asm("{ .reg .u64 t; cvta.to.shared.u64 t, %1; cvt.u32.u64 %0, t; }" : "=r"(a) : "l"(p));
    return a;
}
__device__ __forceinline__ void cp16(uint32_t dst, const void* src) {
    asm volatile("cp.async.cg.shared.global [%0], [%1], 16;" :: "r"(dst), "l"(src));
}
#define CP_COMMIT() asm volatile("cp.async.commit_group;" ::: "memory")
#define CP_WAIT(n)  asm volatile("cp.async.wait_group %0;" :: "n"(n) : "memory")

__device__ __forceinline__ void ldsm4(uint32_t& r0, uint32_t& r1, uint32_t& r2,
                                      uint32_t& r3, uint32_t addr) {
    asm volatile("ldmatrix.sync.aligned.m8n8.x4.shared.b16 {%0,%1,%2,%3}, [%4];"
                 : "=r"(r0), "=r"(r1), "=r"(r2), "=r"(r3) : "r"(addr));
}
__device__ __forceinline__ void mma16816(float* c, const uint32_t* a, const uint32_t* b) {
    asm volatile(
        "mma.sync.aligned.m16n8k16.row.col.f32.f16.f16.f32 "
        "{%0,%1,%2,%3}, {%4,%5,%6,%7}, {%8,%9}, {%0,%1,%2,%3};"
        : "+f"(c[0]), "+f"(c[1]), "+f"(c[2]), "+f"(c[3])
        : "r"(a[0]), "r"(a[1]), "r"(a[2]), "r"(a[3]), "r"(b[0]), "r"(b[1]));
}

// fast accurate tanh: 1 - 2/(exp(2x)+1)
__device__ __forceinline__ float tfast(float x) {
    float e, r;
    asm("ex2.approx.f32 %0, %1;" : "=f"(e) : "f"(x * 2.8853900817779268f));
    asm("rcp.approx.f32 %0, %1;" : "=f"(r) : "f"(e + 1.0f));
    return fmaf(-2.0f, r, 1.0f);
}

// ---------------------------- GEMM stage kernel -----------------------------
// acc[m][n] = sum_k A[m][k]*W[n][k] + bias, opt tanh.
// A, W: single fp16 planes, row stride 512. fp32 accumulation.
// KC=64 chunks (128 B smem rows), warp tile 32x64, 2 CTAs/SM.
template<bool DO_TANH, bool HSF, bool TRANS>
__global__ void __launch_bounds__(NTH, 2) gemm_stage(
    const fp16* __restrict__ A0, const fp16* __restrict__ W0,
    const float* __restrict__ bias0, const float* __restrict__ bias1,
    fp16* __restrict__ outA, float* __restrict__ outF, float* __restrict__ hsf)
{
    extern __shared__ char smem[];
    const uint32_t sb = s2u(smem);
    const int t   = threadIdx.x;
    const int wid = t >> 5;
    const int lid = t & 31;
    const int n0  = blockIdx.x * BN;
    const int m0  = blockIdx.y * BM;
    const int wm  = wid & 3;       // 0..3 (M, 32 rows)
    const int wn  = wid >> 2;      // 0..1 (N, 64 cols)

    if (t < BN) {
        float b = bias0[n0 + t];
        if (bias1) b += bias1[n0 + t];
        ((float*)smem)[t] = b;
    }

    float acc[2][8][4];
#pragma unroll
    for (int mt = 0; mt < 2; ++mt)
#pragma unroll
        for (int nt = 0; nt < 8; ++nt)
#pragma unroll
            for (int e = 0; e < 4; ++e) acc[mt][nt][e] = 0.0f;

    // ldmatrix per-lane addressing (128 B rows: 8 chunk16 columns, swizzle key r&7)
    const int q   = lid >> 3;        // quadrant 0..3
    const int lr8 = lid & 7;
    const int sws = lr8;
    const uint32_t aOff = (uint32_t)((wm * 32 + (q & 1) * 8 + lr8) * 128);
    const int aHalf = q >> 1;
    const uint32_t bOff = (uint32_t)((wn * 64 + (q >> 1) * 8 + lr8) * 128);
    const int bHalf = q & 1;

    const int NC = 8;   // KC=64 chunks over K=512

    auto load_chunk = [&](int cc) {
        const int kc = cc;
        const uint32_t st = sb + 1024 + (uint32_t)(cc % NSTAGE) * STAGE;
#pragma unroll
        for (int i = 0; i < 4; ++i) {                 // A: 128 rows x 8 c16
            int idx = t + i * NTH;
            int r = idx >> 3, c = idx & 7;
            uint32_t d = st + A_OFF + r * 128 + (uint32_t)((c ^ (r & 7)) << 4);
            cp16(d, A0 + (size_t)(m0 + r) * HD + kc * 64 + c * 8);
        }
#pragma unroll
        for (int i = 0; i < 4; ++i) {                 // W: 128 rows x 8 c16
            int idx = t + i * NTH;
            int r = idx >> 3, c = idx & 7;
            uint32_t d = st + W_OFF + r * 128 + (uint32_t)((c ^ (r & 7)) << 4);
            cp16(d, W0 + (size_t)(n0 + r) * HD + kc * 64 + c * 8);
        }
        CP_COMMIT();
    };

    load_chunk(0);
    load_chunk(1);

#pragma unroll 1
    for (int cc = 0; cc < NC; ++cc) {
        if (cc < NC - 1) CP_WAIT(1);
        else             CP_WAIT(0);
        __syncthreads();
        if (cc + 2 < NC) load_chunk(cc + 2);

        const uint32_t st = sb + 1024 + (uint32_t)(cc % NSTAGE) * STAGE;
        const uint32_t aB = st + A_OFF + aOff;
        const uint32_t bB = st + W_OFF + bOff;

#pragma unroll
        for (int ks = 0; ks < 4; ++ks) {
            const uint32_t ca = (uint32_t)(((2 * ks + aHalf) ^ sws) << 4);
            const uint32_t cb = (uint32_t)(((2 * ks + bHalf) ^ sws) << 4);
            uint32_t a[2][4], b[8][2];

#pragma unroll
            for (int bt = 0; bt < 4; ++bt)
                ldsm4(b[2*bt][0], b[2*bt][1], b[2*bt+1][0], b[2*bt+1][1],
                      bB + bt * 2048 + cb);
#pragma unroll
            for (int mt = 0; mt < 2; ++mt)
                ldsm4(a[mt][0], a[mt][1], a[mt][2], a[mt][3],
                      aB + mt * 2048 + ca);
#pragma unroll
            for (int mt = 0; mt < 2; ++mt)
#pragma unroll
                for (int nt = 0; nt < 8; ++nt)
                    mma16816(acc[mt][nt], a[mt], b[nt]);
        }
        __syncthreads();
    }

    // ------------------------------ epilogue --------------------------------
    const float* bsm = (const float*)smem;
    const int lq = lid >> 2;
    const int lr = lid & 3;

#pragma unroll
    for (int mt = 0; mt < 2; ++mt) {
#pragma unroll
        for (int hf = 0; hf < 2; ++hf) {
            const int m = m0 + wm * 32 + mt * 16 + lq + hf * 8;
#pragma unroll
            for (int nt = 0; nt < 8; ++nt) {
                const int n = n0 + wn * 64 + nt * 8 + lr * 2;
                float x0 = acc[mt][nt][hf * 2 + 0] + bsm[n - n0];
                float x1 = acc[mt][nt][hf * 2 + 1] + bsm[n - n0 + 1];
                if (DO_TANH) { x0 = tfast(x0); x1 = tfast(x1); }

                if (TRANS) {
                    const int s = m & 4095, bb = m >> 12;
                    float* dst = outF + ((size_t)(s * 8 + bb)) * HD + n;
                    *(float2*)dst = make_float2(x0, x1);
                } else {
                    __half2 hh;
                    hh.x = __float2half_rn(x0);
                    hh.y = __float2half_rn(x1);
                    *(__half2*)(outA + (size_t)m * HD + n) = hh;
                }
                if (HSF && ((m & 4095) == 4095)) {
                    float* hd = hsf + (size_t)(m >> 12) * HD + n;
                    *(float2*)hd = make_float2(x0, x1);
                }
            }
        }
    }
}

// --------------------------- fused prep kernel -------------------------------
//   blocks [0,128)      : Weff = Whh + Wxh@Why -> fp16 plane (slots 1,2)
//   blocks [128,256)    : beff = bhh + bxh + Wxh@bhy (warp reductions)
//   blocks [256,2304)   : convert X -> g_X (fp16)
//   blocks [2304,2368)  : convert W_xh0 / final projection -> fp16 (slots 0,3)
struct PrepP {
    const float* Wxh[2];
    const float* Why[2];
    const float* Whh[2];
    fp16*        WeffC[2];
    const float* bhh[2];
    const float* bxh[2];
    const float* bhy[2];
    float*       beff[2];
    const float* xs;
    fp16*        X;
    const float* Wraw[2];
    fp16*        Wbase;
};

__device__ void prep_weff(const PrepP& p, int id, int t)
{
    const int l  = id >> 6;
    const int rm = id & 63;
    const int m0 = (rm >> 3) * 64;
    const int n0 = (rm & 7) * 64;
    const float* __restrict__ A = p.Wxh[l];
    const float* __restrict__ B = p.Why[l];
    const float* __restrict__ Wadd = p.Whh[l];
    fp16* __restrict__ C = p.WeffC[l];

    __shared__ float As[16][64];
    __shared__ float Bs[16][64];
    const int tx = t & 15, ty = t >> 4;

    float acc[4][4] = {};
#pragma unroll 1
    for (int kt = 0; kt < 512; kt += 16) {
#pragma unroll
        for (int e = t; e < 1024; e += 256) {
            int am = e >> 4, ak = e & 15;
            As[ak][am] = A[(size_t)(m0 + am) * 512 + kt + ak];
            int bj = e & 63, bk = e >> 6;
            Bs[bk][bj] = B[(size_t)(kt + bk) * 512 + n0 + bj];
        }
        __syncthreads();
#pragma unroll
        for (int k = 0; k < 16; ++k) {
            float af[4], bf[4];
#pragma unroll
            for (int i = 0; i < 4; ++i) af[i] = As[k][ty * 4 + i];
#pragma unroll
            for (int j = 0; j < 4; ++j) bf[j] = Bs[k][tx * 4 + j];
#pragma unroll
            for (int i = 0; i < 4; ++i)
#pragma unroll
                for (int j = 0; j < 4; ++j)
                    acc[i][j] = fmaf(af[i], bf[j], acc[i][j]);
        }
        __syncthreads();
    }

    const int kcol = n0 + tx * 4;
#pragma unroll
    for (int i = 0; i < 4; ++i) {
        const int n = m0 + ty * 4 + i;
        fp16 h4[4];
#pragma unroll
        for (int j = 0; j < 4; ++j)
            h4[j] = __float2half_rn(Wadd[(size_t)n * 512 + kcol + j] + acc[i][j]);
        *(uint2*)(C + (size_t)n * 512 + kcol) = *(uint2*)h4;
    }
}

__device__ void prep_beff(const PrepP& p, int id, int t)
{
    const int gw = id * 8 + (t >> 5);
    const int l = gw >> 9;
    const int n = gw & 511;
    const int lane = t & 31;
    const float* W  = p.Wxh[l] + (size_t)n * 512 + lane * 16;
    const float* bh = p.bhy[l] + lane * 16;
    float s = 0.0f;
#pragma unroll
    for (int k = 0; k < 16; k += 4) {
        float4 w = *(const float4*)(W + k);
        float4 b = *(const float4*)(bh + k);
        s = fmaf(w.x, b.x, s); s = fmaf(w.y, b.y, s);
        s = fmaf(w.z, b.z, s); s = fmaf(w.w, b.w, s);
    }
#pragma unroll
    for (int o = 16; o; o >>= 1) s += __shfl_xor_sync(0xFFFFFFFFu, s, o);
    if (lane == 0) p.beff[l][n] = p.bhh[l][n] + p.bxh[l][n] + s;
}

__device__ void prep_cvt(const float* __restrict__ src0, fp16* __restrict__ d)
{
    uint32_t h[16];
#pragma unroll
    for (int j = 0; j < 8; ++j) {
        float4 v = *(const float4*)(src0 + j * 4);
        __half2 h0, h1;
        h0.x = __float2half_rn(v.x); h0.y = __float2half_rn(v.y);
        h1.x = __float2half_rn(v.z); h1.y = __float2half_rn(v.w);
        h[2*j] = *(uint32_t*)&h0; h[2*j+1] = *(uint32_t*)&h1;
    }
#pragma unroll
    for (int j = 0; j < 4; ++j)
        ((uint4*)d)[j] = *(uint4*)(h + 4*j);
}

__global__ void __launch_bounds__(256) k_prep(PrepP p)
{
    const int bid = blockIdx.x;
    const int t   = threadIdx.x;

    if (bid < 128) {
        prep_weff(p, bid, t);
    } else if (bid < 256) {
        prep_beff(p, bid - 128, t);
    } else if (bid < 2304) {
        const size_t off = ((size_t)(bid - 256) * 256 + t) * 32;
        prep_cvt(p.xs + off, p.X + off);
    } else {
        const size_t idx = (size_t)(bid - 2304) * 256 + t;
        const int slot = (int)(idx >> 13);           // 0 or 1
        const size_t off = (idx & 8191) * 32;
        prep_cvt(p.Wraw[slot] + off,
                 p.Wbase + (size_t)(slot * 3) * WELEMS + off);
    }
}

// --------------------------------- launcher ---------------------------------
extern "C" void kernel_launch(void* const* d_in, const int* in_sizes, int n_in,
                              void* d_out, int out_size)
{
    const float* xs     = (const float*)d_in[0];
    const float* W_xh0  = (const float*)d_in[1];
    const float* b_xh0  = (const float*)d_in[2];
    const float* b_hh0  = (const float*)d_in[4];
    const float* W_hy0  = (const float*)d_in[5];
    const float* b_hy0  = (const float*)d_in[6];
    const float* W_xh_h = (const float*)d_in[7];
    const float* b_xh_h = (const float*)d_in[8];
    const float* W_hh_h = (const float*)d_in[9];
    const float* b_hh_h = (const float*)d_in[10];
    const float* W_hy_h = (const float*)d_in[11];
    const float* b_hy_h = (const float*)d_in[12];

    float* out = (float*)d_out;
    float* hs_final = out + (size_t)4096 * 8 * HD;

    fp16 *X, *H0, *H1, *Wb;
    float *beff;
    cudaGetSymbolAddress((void**)&X,   g_X);
    cudaGetSymbolAddress((void**)&H0,  g_H0);
    cudaGetSymbolAddress((void**)&H1,  g_H1);
    cudaGetSymbolAddress((void**)&Wb,  g_W);
    cudaGetSymbolAddress((void**)&beff, g_beff);

    cudaFuncSetAttribute(gemm_stage<true,  false, false>,
                         cudaFuncAttributeMaxDynamicSharedMemorySize, SMEMB);
    cudaFuncSetAttribute(gemm_stage<true,  true,  false>,
                         cudaFuncAttributeMaxDynamicSharedMemorySize, SMEMB);
    cudaFuncSetAttribute(gemm_stage<false, false, true >,
                         cudaFuncAttributeMaxDynamicSharedMemorySize, SMEMB);

#define WS(s) (Wb + (size_t)(s) * WELEMS)

    // ---- fused prep ----
    PrepP pp;
    pp.Wxh[0] = W_xh_h;      pp.Wxh[1] = W_xh_h + WSZ;
    pp.Why[0] = W_hy0;       pp.Why[1] = W_hy_h;
    pp.Whh[0] = W_hh_h;      pp.Whh[1] = W_hh_h + WSZ;
    pp.WeffC[0] = WS(1);     pp.WeffC[1] = WS(2);
    pp.bhh[0] = b_hh_h;      pp.bhh[1] = b_hh_h + HD;
    pp.bxh[0] = b_xh_h;      pp.bxh[1] = b_xh_h + HD;
    pp.bhy[0] = b_hy0;       pp.bhy[1] = b_hy_h;
    pp.beff[0] = beff;       pp.beff[1] = beff + HD;
    pp.xs = xs;
    pp.X  = X;
    pp.Wraw[0] = W_xh0;
    pp.Wraw[1] = W_hy_h + WSZ;
    pp.Wbase = Wb;
    k_prep<<<2368, 256>>>(pp);

    dim3 grid(HD / BN, MROWS / BM);   // (4, 256) = 1024 CTAs
    dim3 block(NTH);

    // 1) h0 = tanh(X @ W_xh0^T + b_xh0 + b_hh0)
    gemm_stage<true, false, false><<<grid, block, SMEMB>>>(
        X, WS(0), b_xh0, b_hh0, H0, nullptr, nullptr);
    // 2) h1 = tanh(h0 @ Weff0^T + beff0)
    gemm_stage<true, false, false><<<grid, block, SMEMB>>>(
        H0, WS(1), beff, nullptr, H1, nullptr, nullptr);
    // 3) h2 = tanh(h1 @ Weff1^T + beff1)  (+ hs_final)
    gemm_stage<true, true, false><<<grid, block, SMEMB>>>(
        H1, WS(2), beff + HD, nullptr, H0, nullptr, hs_final);
    // 4) outputs = (h2 @ W_hy_h[1]^T + b_hy_h[1]) -> [S, B, H] fp32
    gemm_stage<false, false, true><<<grid, block, SMEMB>>>(
        H0, WS(3), b_hy_h + HD, nullptr, nullptr, out, nullptr);
#undef WS
}

// round 15
// speedup vs baseline: 1.5025x; 1.0160x over previous
#include <cuda_runtime.h>
#include <cuda_fp16.h>
#include <math.h>
#include <cstdint>
#include <cstddef>

typedef __half fp16;

#define MROWS 32768
#define HD    512
#define WSZ   (512*512)
#define WELEMS  ((size_t)WSZ)

#define BM 128
#define BN 128
#define NTH 256

// smem: 1024 B header (bias) + 3 stages x 32 KB (A 16K + W 16K, KC=64)
#define A_OFF  0u
#define W_OFF  16384u
#define STAGE  32768u
#define NSTAGE 3
#define SMEMB  (1024u + NSTAGE*STAGE)   // 99328

// ------------- scratch (static device arrays, no runtime alloc) -------------
__device__ fp16  g_X [(size_t)MROWS * HD];
__device__ fp16  g_H0[(size_t)MROWS * HD];
__device__ fp16  g_H1[(size_t)MROWS * HD];
__device__ fp16  g_W [4 * WELEMS];
__device__ float g_beff[2 * HD];

// ----------------------------- PTX helpers ----------------------------------
__device__ __forceinline__ uint32_t s2u(const void* p) {
    uint32_t a;
    asm("{ .reg .u64 t; cvta.to.shared.u64 t, %1; cvt.u32.u64 %0, t; }" : "=r"(a) : "l"(p));
    return a;
}
__device__ __forceinline__ void cp16(uint32_t dst, const void* src) {
    asm volatile("cp.async.cg.shared.global [%0], [%1], 16;" :: "r"(dst), "l"(src));
}
#define CP_COMMIT() asm volatile("cp.async.commit_group;" ::: "memory")
#define CP_WAIT(n)  asm volatile("cp.async.wait_group %0;" :: "n"(n) : "memory")

__device__ __forceinline__ void ldsm4(uint32_t& r0, uint32_t& r1, uint32_t& r2,
                                      uint32_t& r3, uint32_t addr) {
    asm volatile("ldmatrix.sync.aligned.m8n8.x4.shared.b16 {%0,%1,%2,%3}, [%4];"
                 : "=r"(r0), "=r"(r1), "=r"(r2), "=r"(r3) : "r"(addr));
}
__device__ __forceinline__ void mma16816(float* c, const uint32_t* a, const uint32_t* b) {
    asm volatile(
        "mma.sync.aligned.m16n8k16.row.col.f32.f16.f16.f32 "
        "{%0,%1,%2,%3}, {%4,%5,%6,%7}, {%8,%9}, {%0,%1,%2,%3};"
        : "+f"(c[0]), "+f"(c[1]), "+f"(c[2]), "+f"(c[3])
        : "r"(a[0]), "r"(a[1]), "r"(a[2]), "r"(a[3]), "r"(b[0]), "r"(b[1]));
}

// fast accurate tanh: 1 - 2/(exp(2x)+1)
__device__ __forceinline__ float tfast(float x) {
    float e, r;
    asm("ex2.approx.f32 %0, %1;" : "=f"(e) : "f"(x * 2.8853900817779268f));
    asm("rcp.approx.f32 %0, %1;" : "=f"(r) : "f"(e + 1.0f));
    return fmaf(-2.0f, r, 1.0f);
}

// ---------------------------- GEMM stage kernel -----------------------------
// acc[m][n] = sum_k A[m][k]*W[n][k] + bias, opt tanh.
// A, W: single fp16 planes, row stride 512. fp32 accumulation.
// KC=64 chunks (128 B smem rows), warp tile 32x64, 2 CTAs/SM.
// ONE barrier per chunk: with NSTAGE=3 / lookahead 2, load(cc+2) overwrites the
// stage last read by compute(cc-1), which the top-of-iteration barrier already
// ordered. The trailing barrier R14 carried was redundant.
template<bool DO_TANH, bool HSF, bool TRANS>
__global__ void __launch_bounds__(NTH, 2) gemm_stage(
    const fp16* __restrict__ A0, const fp16* __restrict__ W0,
    const float* __restrict__ bias0, const float* __restrict__ bias1,
    fp16* __restrict__ outA, float* __restrict__ outF, float* __restrict__ hsf)
{
    extern __shared__ char smem[];
    const uint32_t sb = s2u(smem);
    const int t   = threadIdx.x;
    const int wid = t >> 5;
    const int lid = t & 31;
    const int n0  = blockIdx.x * BN;
    const int m0  = blockIdx.y * BM;
    const int wm  = wid & 3;       // 0..3 (M, 32 rows)
    const int wn  = wid >> 2;      // 0..1 (N, 64 cols)

    if (t < BN) {
        float b = bias0[n0 + t];
        if (bias1) b += bias1[n0 + t];
        ((float*)smem)[t] = b;
    }

    float acc[2][8][4];
#pragma unroll
    for (int mt = 0; mt < 2; ++mt)
#pragma unroll
        for (int nt = 0; nt < 8; ++nt)
#pragma unroll
            for (int e = 0; e < 4; ++e) acc[mt][nt][e] = 0.0f;

    // ldmatrix per-lane addressing (128 B rows: 8 chunk16 columns, swizzle key r&7)
    const int q   = lid >> 3;        // quadrant 0..3
    const int lr8 = lid & 7;
    const int sws = lr8;
    const uint32_t aOff = (uint32_t)((wm * 32 + (q & 1) * 8 + lr8) * 128);
    const int aHalf = q >> 1;
    const uint32_t bOff = (uint32_t)((wn * 64 + (q >> 1) * 8 + lr8) * 128);
    const int bHalf = q & 1;

    const int NC = 8;   // KC=64 chunks over K=512

    auto load_chunk = [&](int cc, uint32_t st) {
        const int kc = cc;
#pragma unroll
        for (int i = 0; i < 4; ++i) {                 // A: 128 rows x 8 c16
            int idx = t + i * NTH;
            int r = idx >> 3, c = idx & 7;
            uint32_t d = st + A_OFF + r * 128 + (uint32_t)((c ^ (r & 7)) << 4);
            cp16(d, A0 + (size_t)(m0 + r) * HD + kc * 64 + c * 8);
        }
#pragma unroll
        for (int i = 0; i < 4; ++i) {                 // W: 128 rows x 8 c16
            int idx = t + i * NTH;
            int r = idx >> 3, c = idx & 7;
            uint32_t d = st + W_OFF + r * 128 + (uint32_t)((c ^ (r & 7)) << 4);
            cp16(d, W0 + (size_t)(n0 + r) * HD + kc * 64 + c * 8);
        }
        CP_COMMIT();
    };

    load_chunk(0, sb + 1024);
    load_chunk(1, sb + 1024 + STAGE);

    int stage_c = 0;                         // stage of chunk cc
    int stage_l = 2;                         // stage for chunk cc+2
#pragma unroll 1
    for (int cc = 0; cc < NC; ++cc) {
        if (cc < NC - 1) CP_WAIT(1);
        else             CP_WAIT(0);
        __syncthreads();
        if (cc + 2 < NC) {
            load_chunk(cc + 2, sb + 1024 + (uint32_t)stage_l * STAGE);
            stage_l = (stage_l == 2) ? 0 : stage_l + 1;
        }

        const uint32_t st = sb + 1024 + (uint32_t)stage_c * STAGE;
        stage_c = (stage_c == 2) ? 0 : stage_c + 1;
        const uint32_t aB = st + A_OFF + aOff;
        const uint32_t bB = st + W_OFF + bOff;

#pragma unroll
        for (int ks = 0; ks < 4; ++ks) {
            const uint32_t ca = (uint32_t)(((2 * ks + aHalf) ^ sws) << 4);
            const uint32_t cb = (uint32_t)(((2 * ks + bHalf) ^ sws) << 4);
            uint32_t a[2][4], b[8][2];

#pragma unroll
            for (int bt = 0; bt < 4; ++bt)
                ldsm4(b[2*bt][0], b[2*bt][1], b[2*bt+1][0], b[2*bt+1][1],
                      bB + bt * 2048 + cb);
#pragma unroll
            for (int mt = 0; mt < 2; ++mt)
                ldsm4(a[mt][0], a[mt][1], a[mt][2], a[mt][3],
                      aB + mt * 2048 + ca);
#pragma unroll
            for (int mt = 0; mt < 2; ++mt)
#pragma unroll
                for (int nt = 0; nt < 8; ++nt)
                    mma16816(acc[mt][nt], a[mt], b[nt]);
        }
    }

    // ------------------------------ epilogue --------------------------------
    const float* bsm = (const float*)smem;
    const int lq = lid >> 2;
    const int lr = lid & 3;

#pragma unroll
    for (int mt = 0; mt < 2; ++mt) {
#pragma unroll
        for (int hf = 0; hf < 2; ++hf) {
            const int m = m0 + wm * 32 + mt * 16 + lq + hf * 8;
#pragma unroll
            for (int nt = 0; nt < 8; ++nt) {
                const int n = n0 + wn * 64 + nt * 8 + lr * 2;
                float x0 = acc[mt][nt][hf * 2 + 0] + bsm[n - n0];
                float x1 = acc[mt][nt][hf * 2 + 1] + bsm[n - n0 + 1];
                if (DO_TANH) { x0 = tfast(x0); x1 = tfast(x1); }

                if (TRANS) {
                    const int s = m & 4095, bb = m >> 12;
                    float* dst = outF + ((size_t)(s * 8 + bb)) * HD + n;
                    *(float2*)dst = make_float2(x0, x1);
                } else {
                    __half2 hh;
                    hh.x = __float2half_rn(x0);
                    hh.y = __float2half_rn(x1);
                    *(__half2*)(outA + (size_t)m * HD + n) = hh;
                }
                if (HSF && ((m & 4095) == 4095)) {
                    float* hd = hsf + (size_t)(m >> 12) * HD + n;
                    *(float2*)hd = make_float2(x0, x1);
                }
            }
        }
    }
}

// --------------------------- fused prep kernel -------------------------------
//   blocks [0,128)      : Weff = Whh + Wxh@Why -> fp16 plane (slots 1,2)
//   blocks [128,256)    : beff = bhh + bxh + Wxh@bhy (warp reductions)
//   blocks [256,2304)   : convert X -> g_X (fp16)
//   blocks [2304,2368)  : convert W_xh0 / final projection -> fp16 (slots 0,3)
struct PrepP {
    const float* Wxh[2];
    const float* Why[2];
    const float* Whh[2];
    fp16*        WeffC[2];
    const float* bhh[2];
    const float* bxh[2];
    const float* bhy[2];
    float*       beff[2];
    const float* xs;
    fp16*        X;
    const float* Wraw[2];
    fp16*        Wbase;
};

__device__ void prep_weff(const PrepP& p, int id, int t)
{
    const int l  = id >> 6;
    const int rm = id & 63;
    const int m0 = (rm >> 3) * 64;
    const int n0 = (rm & 7) * 64;
    const float* __restrict__ A = p.Wxh[l];
    const float* __restrict__ B = p.Why[l];
    const float* __restrict__ Wadd = p.Whh[l];
    fp16* __restrict__ C = p.WeffC[l];

    __shared__ float As[16][64];
    __shared__ float Bs[16][64];
    const int tx = t & 15, ty = t >> 4;

    float acc[4][4] = {};
#pragma unroll 1
    for (int kt = 0; kt < 512; kt += 16) {
#pragma unroll
        for (int e = t; e < 1024; e += 256) {
            int am = e >> 4, ak = e & 15;
            As[ak][am] = A[(size_t)(m0 + am) * 512 + kt + ak];
            int bj = e & 63, bk = e >> 6;
            Bs[bk][bj] = B[(size_t)(kt + bk) * 512 + n0 + bj];
        }
        __syncthreads();
#pragma unroll
        for (int k = 0; k < 16; ++k) {
            float af[4], bf[4];
#pragma unroll
            for (int i = 0; i < 4; ++i) af[i] = As[k][ty * 4 + i];
#pragma unroll
            for (int j = 0; j < 4; ++j) bf[j] = Bs[k][tx * 4 + j];
#pragma unroll
            for (int i = 0; i < 4; ++i)
#pragma unroll
                for (int j = 0; j < 4; ++j)
                    acc[i][j] = fmaf(af[i], bf[j], acc[i][j]);
        }
        __syncthreads();
    }

    const int kcol = n0 + tx * 4;
#pragma unroll
    for (int i = 0; i < 4; ++i) {
        const int n = m0 + ty * 4 + i;
        fp16 h4[4];
#pragma unroll
        for (int j = 0; j < 4; ++j)
            h4[j] = __float2half_rn(Wadd[(size_t)n * 512 + kcol + j] + acc[i][j]);
        *(uint2*)(C + (size_t)n * 512 + kcol) = *(uint2*)h4;
    }
}

__device__ void prep_beff(const PrepP& p, int id, int t)
{
    const int gw = id * 8 + (t >> 5);
    const int l = gw >> 9;
    const int n = gw & 511;
    const int lane = t & 31;
    const float* W  = p.Wxh[l] + (size_t)n * 512 + lane * 16;
    const float* bh = p.bhy[l] + lane * 16;
    float s = 0.0f;
#pragma unroll
    for (int k = 0; k < 16; k += 4) {
        float4 w = *(const float4*)(W + k);
        float4 b = *(const float4*)(bh + k);
        s = fmaf(w.x, b.x, s); s = fmaf(w.y, b.y, s);
        s = fmaf(w.z, b.z, s); s = fmaf(w.w, b.w, s);
    }
#pragma unroll
    for (int o = 16; o; o >>= 1) s += __shfl_xor_sync(0xFFFFFFFFu, s, o);
    if (lane == 0) p.beff[l][n] = p.bhh[l][n] + p.bxh[l][n] + s;
}

__device__ void prep_cvt(const float* __restrict__ src0, fp16* __restrict__ d)
{
    uint32_t h[16];
#pragma unroll
    for (int j = 0; j < 8; ++j) {
        float4 v = *(const float4*)(src0 + j * 4);
        __half2 h0, h1;
        h0.x = __float2half_rn(v.x); h0.y = __float2half_rn(v.y);
        h1.x = __float2half_rn(v.z); h1.y = __float2half_rn(v.w);
        h[2*j] = *(uint32_t*)&h0; h[2*j+1] = *(uint32_t*)&h1;
    }
#pragma unroll
    for (int j = 0; j < 4; ++j)
        ((uint4*)d)[j] = *(uint4*)(h + 4*j);
}

__global__ void __launch_bounds__(256) k_prep(PrepP p)
{
    const int bid = blockIdx.x;
    const int t   = threadIdx.x;

    if (bid < 128) {
        prep_weff(p, bid, t);
    } else if (bid < 256) {
        prep_beff(p, bid - 128, t);
    } else if (bid < 2304) {
        const size_t off = ((size_t)(bid - 256) * 256 + t) * 32;
        prep_cvt(p.xs + off, p.X + off);
    } else {
        const size_t idx = (size_t)(bid - 2304) * 256 + t;
        const int slot = (int)(idx >> 13);           // 0 or 1
        const size_t off = (idx & 8191) * 32;
        prep_cvt(p.Wraw[slot] + off,
                 p.Wbase + (size_t)(slot * 3) * WELEMS + off);
    }
}

// --------------------------------- launcher ---------------------------------
extern "C" void kernel_launch(void* const* d_in, const int* in_sizes, int n_in,
                              void* d_out, int out_size)
{
    const float* xs     = (const float*)d_in[0];
    const float* W_xh0  = (const float*)d_in[1];
    const float* b_xh0  = (const float*)d_in[2];
    const float* b_hh0  = (const float*)d_in[4];
    const float* W_hy0  = (const float*)d_in[5];
    const float* b_hy0  = (const float*)d_in[6];
    const float* W_xh_h = (const float*)d_in[7];
    const float* b_xh_h = (const float*)d_in[8];
    const float* W_hh_h = (const float*)d_in[9];
    const float* b_hh_h = (const float*)d_in[10];
    const float* W_hy_h = (const float*)d_in[11];
    const float* b_hy_h = (const float*)d_in[12];

    float* out = (float*)d_out;
    float* hs_final = out + (size_t)4096 * 8 * HD;

    fp16 *X, *H0, *H1, *Wb;
    float *beff;
    cudaGetSymbolAddress((void**)&X,   g_X);
    cudaGetSymbolAddress((void**)&H0,  g_H0);
    cudaGetSymbolAddress((void**)&H1,  g_H1);
    cudaGetSymbolAddress((void**)&Wb,  g_W);
    cudaGetSymbolAddress((void**)&beff, g_beff);

    cudaFuncSetAttribute(gemm_stage<true,  false, false>,
                         cudaFuncAttributeMaxDynamicSharedMemorySize, SMEMB);
    cudaFuncSetAttribute(gemm_stage<true,  true,  false>,
                         cudaFuncAttributeMaxDynamicSharedMemorySize, SMEMB);
    cudaFuncSetAttribute(gemm_stage<false, false, true >,
                         cudaFuncAttributeMaxDynamicSharedMemorySize, SMEMB);

#define WS(s) (Wb + (size_t)(s) * WELEMS)

    // ---- fused prep ----
    PrepP pp;
    pp.Wxh[0] = W_xh_h;      pp.Wxh[1] = W_xh_h + WSZ;
    pp.Why[0] = W_hy0;       pp.Why[1] = W_hy_h;
    pp.Whh[0] = W_hh_h;      pp.Whh[1] = W_hh_h + WSZ;
    pp.WeffC[0] = WS(1);     pp.WeffC[1] = WS(2);
    pp.bhh[0] = b_hh_h;      pp.bhh[1] = b_hh_h + HD;
    pp.bxh[0] = b_xh_h;      pp.bxh[1] = b_xh_h + HD;
    pp.bhy[0] = b_hy0;       pp.bhy[1] = b_hy_h;
    pp.beff[0] = beff;       pp.beff[1] = beff + HD;
    pp.xs = xs;
    pp.X  = X;
    pp.Wraw[0] = W_xh0;
    pp.Wraw[1] = W_hy_h + WSZ;
    pp.Wbase = Wb;
    k_prep<<<2368, 256>>>(pp);

    dim3 grid(HD / BN, MROWS / BM);   // (4, 256) = 1024 CTAs
    dim3 block(NTH);

    // 1) h0 = tanh(X @ W_xh0^T + b_xh0 + b_hh0)
    gemm_stage<true, false, false><<<grid, block, SMEMB>>>(
        X, WS(0), b_xh0, b_hh0, H0, nullptr, nullptr);
    // 2) h1 = tanh(h0 @ Weff0^T + beff0)
    gemm_stage<true, false, false><<<grid, block, SMEMB>>>(
        H0, WS(1), beff, nullptr, H1, nullptr, nullptr);
    // 3) h2 = tanh(h1 @ Weff1^T + beff1)  (+ hs_final)
    gemm_stage<true, true, false><<<grid, block, SMEMB>>>(
        H1, WS(2), beff + HD, nullptr, H0, nullptr, hs_final);
    // 4) outputs = (h2 @ W_hy_h[1]^T + b_hy_h[1]) -> [S, B, H] fp32
    gemm_stage<false, false, true><<<grid, block, SMEMB>>>(
        H0, WS(3), b_hy_h + HD, nullptr, nullptr, out, nullptr);
#undef WS
}

// round 16
// speedup vs baseline: 1.5774x; 1.0498x over previous
#include <cuda_runtime.h>
#include <cuda_fp16.h>
#include <math.h>
#include <cstdint>
#include <cstddef>

typedef __half fp16;

#define MROWS 32768
#define HD    512
#define WSZ   (512*512)
#define WELEMS  ((size_t)WSZ)

#define BM 128
#define BN 128
#define NTH 256

// smem: 1024 B header (bias) + 3 stages x 32 KB (A 16K + W 16K, KC=64)
#define A_OFF  0u
#define W_OFF  16384u
#define STAGE  32768u
#define NSTAGE 3
#define SMEMB  (1024u + NSTAGE*STAGE)   // 99328

// ------------- scratch (static device arrays, no runtime alloc) -------------
__device__ fp16  g_X [(size_t)MROWS * HD];
__device__ fp16  g_H0[(size_t)MROWS * HD];
__device__ fp16  g_H1[(size_t)MROWS * HD];
__device__ fp16  g_W [4 * WELEMS];
__device__ float g_beff[2 * HD];

// ----------------------------- PTX helpers ----------------------------------
__device__ __forceinline__ uint32_t s2u(const void* p) {
    uint32_t a;
    asm("{ .reg .u64 t; cvta.to.shared.u64 t, %1; cvt.u32.u64 %0, t; }" : "=r"(a) : "l"(p));
    return a;
}
__device__ __forceinline__ void cp16(uint32_t dst, const void* src) {
    asm volatile("cp.async.cg.shared.global [%0], [%1], 16;" :: "r"(dst), "l"(src));
}
#define CP_COMMIT() asm volatile("cp.async.commit_group;" ::: "memory")
#define CP_WAIT(n)  asm volatile("cp.async.wait_group %0;" :: "n"(n) : "memory")

__device__ __forceinline__ void ldsm4(uint32_t& r0, uint32_t& r1, uint32_t& r2,
                                      uint32_t& r3, uint32_t addr) {
    asm volatile("ldmatrix.sync.aligned.m8n8.x4.shared.b16 {%0,%1,%2,%3}, [%4];"
                 : "=r"(r0), "=r"(r1), "=r"(r2), "=r"(r3) : "r"(addr));
}
__device__ __forceinline__ void mma16816(float* c, const uint32_t* a, const uint32_t* b) {
    asm volatile(
        "mma.sync.aligned.m16n8k16.row.col.f32.f16.f16.f32 "
        "{%0,%1,%2,%3}, {%4,%5,%6,%7}, {%8,%9}, {%0,%1,%2,%3};"
        : "+f"(c[0]), "+f"(c[1]), "+f"(c[2]), "+f"(c[3])
        : "r"(a[0]), "r"(a[1]), "r"(a[2]), "r"(a[3]), "r"(b[0]), "r"(b[1]));
}

// fast accurate tanh: 1 - 2/(exp(2x)+1)
__device__ __forceinline__ float tfast(float x) {
    float e, r;
    asm("ex2.approx.f32 %0, %1;" : "=f"(e) : "f"(x * 2.8853900817779268f));
    asm("rcp.approx.f32 %0, %1;" : "=f"(r) : "f"(e + 1.0f));
    return fmaf(-2.0f, r, 1.0f);
}

// ---------------------------- GEMM stage kernel -----------------------------
// acc[m][n] = sum_k A[m][k]*W[n][k] + bias, opt tanh.
// A, W: single fp16 planes, row stride 512. fp32 accumulation.
// KC=64 chunks (128 B smem rows), warp tile 32x64, 2 CTAs/SM, 1 barrier/chunk.
template<bool DO_TANH, bool HSF, bool TRANS>
__global__ void __launch_bounds__(NTH, 2) gemm_stage(
    const fp16* __restrict__ A0, const fp16* __restrict__ W0,
    const float* __restrict__ bias0, const float* __restrict__ bias1,
    fp16* __restrict__ outA, float* __restrict__ outF, float* __restrict__ hsf)
{
    extern __shared__ char smem[];
    const uint32_t sb = s2u(smem);
    const int t   = threadIdx.x;
    const int wid = t >> 5;
    const int lid = t & 31;
    const int n0  = blockIdx.x * BN;
    const int m0  = blockIdx.y * BM;
    const int wm  = wid & 3;       // 0..3 (M, 32 rows)
    const int wn  = wid >> 2;      // 0..1 (N, 64 cols)

    if (t < BN) {
        float b = bias0[n0 + t];
        if (bias1) b += bias1[n0 + t];
        ((float*)smem)[t] = b;
    }

    float acc[2][8][4];
#pragma unroll
    for (int mt = 0; mt < 2; ++mt)
#pragma unroll
        for (int nt = 0; nt < 8; ++nt)
#pragma unroll
            for (int e = 0; e < 4; ++e) acc[mt][nt][e] = 0.0f;

    // ldmatrix per-lane addressing (128 B rows: 8 chunk16 columns, swizzle key r&7)
    const int q   = lid >> 3;        // quadrant 0..3
    const int lr8 = lid & 7;
    const int sws = lr8;
    const uint32_t aOff = (uint32_t)((wm * 32 + (q & 1) * 8 + lr8) * 128);
    const int aHalf = q >> 1;
    const uint32_t bOff = (uint32_t)((wn * 64 + (q >> 1) * 8 + lr8) * 128);
    const int bHalf = q & 1;

    const int NC = 8;   // KC=64 chunks over K=512

    auto load_chunk = [&](int cc, uint32_t st) {
        const int kc = cc;
#pragma unroll
        for (int i = 0; i < 4; ++i) {                 // A: 128 rows x 8 c16
            int idx = t + i * NTH;
            int r = idx >> 3, c = idx & 7;
            uint32_t d = st + A_OFF + r * 128 + (uint32_t)((c ^ (r & 7)) << 4);
            cp16(d, A0 + (size_t)(m0 + r) * HD + kc * 64 + c * 8);
        }
#pragma unroll
        for (int i = 0; i < 4; ++i) {                 // W: 128 rows x 8 c16
            int idx = t + i * NTH;
            int r = idx >> 3, c = idx & 7;
            uint32_t d = st + W_OFF + r * 128 + (uint32_t)((c ^ (r & 7)) << 4);
            cp16(d, W0 + (size_t)(n0 + r) * HD + kc * 64 + c * 8);
        }
        CP_COMMIT();
    };

    load_chunk(0, sb + 1024);
    load_chunk(1, sb + 1024 + STAGE);

    int stage_c = 0;                         // stage of chunk cc
    int stage_l = 2;                         // stage for chunk cc+2
#pragma unroll 1
    for (int cc = 0; cc < NC; ++cc) {
        if (cc < NC - 1) CP_WAIT(1);
        else             CP_WAIT(0);
        __syncthreads();
        if (cc + 2 < NC) {
            load_chunk(cc + 2, sb + 1024 + (uint32_t)stage_l * STAGE);
            stage_l = (stage_l == 2) ? 0 : stage_l + 1;
        }

        const uint32_t st = sb + 1024 + (uint32_t)stage_c * STAGE;
        stage_c = (stage_c == 2) ? 0 : stage_c + 1;
        const uint32_t aB = st + A_OFF + aOff;
        const uint32_t bB = st + W_OFF + bOff;

#pragma unroll
        for (int ks = 0; ks < 4; ++ks) {
            const uint32_t ca = (uint32_t)(((2 * ks + aHalf) ^ sws) << 4);
            const uint32_t cb = (uint32_t)(((2 * ks + bHalf) ^ sws) << 4);
            uint32_t a[2][4], b[8][2];

#pragma unroll
            for (int bt = 0; bt < 4; ++bt)
                ldsm4(b[2*bt][0], b[2*bt][1], b[2*bt+1][0], b[2*bt+1][1],
                      bB + bt * 2048 + cb);
#pragma unroll
            for (int mt = 0; mt < 2; ++mt)
                ldsm4(a[mt][0], a[mt][1], a[mt][2], a[mt][3],
                      aB + mt * 2048 + ca);
#pragma unroll
            for (int mt = 0; mt < 2; ++mt)
#pragma unroll
                for (int nt = 0; nt < 8; ++nt)
                    mma16816(acc[mt][nt], a[mt], b[nt]);
        }
    }

    // ------------------------------ epilogue --------------------------------
    const float* bsm = (const float*)smem;
    const int lq = lid >> 2;
    const int lr = lid & 3;

#pragma unroll
    for (int mt = 0; mt < 2; ++mt) {
#pragma unroll
        for (int hf = 0; hf < 2; ++hf) {
            const int m = m0 + wm * 32 + mt * 16 + lq + hf * 8;
#pragma unroll
            for (int nt = 0; nt < 8; ++nt) {
                const int n = n0 + wn * 64 + nt * 8 + lr * 2;
                float x0 = acc[mt][nt][hf * 2 + 0] + bsm[n - n0];
                float x1 = acc[mt][nt][hf * 2 + 1] + bsm[n - n0 + 1];
                if (DO_TANH) { x0 = tfast(x0); x1 = tfast(x1); }

                if (TRANS) {
                    const int s = m & 4095, bb = m >> 12;
                    float* dst = outF + ((size_t)(s * 8 + bb)) * HD + n;
                    *(float2*)dst = make_float2(x0, x1);
                } else {
                    __half2 hh;
                    hh.x = __float2half_rn(x0);
                    hh.y = __float2half_rn(x1);
                    *(__half2*)(outA + (size_t)m * HD + n) = hh;
                }
                if (HSF && ((m & 4095) == 4095)) {
                    float* hd = hsf + (size_t)(m >> 12) * HD + n;
                    *(float2*)hd = make_float2(x0, x1);
                }
            }
        }
    }
}

// --------------------------- fused prep kernel -------------------------------
//   blocks [0,128)      : Weff = Whh + Wxh@Why -> fp16 plane (slots 1,2)
//   blocks [128,256)    : beff = bhh + bxh + Wxh@bhy (warp reductions)
//   blocks [256,2304)   : convert X -> g_X (fp16), coalesced
//   blocks [2304,2368)  : convert W_xh0 / final projection -> fp16 (slots 0,3)
struct PrepP {
    const float* Wxh[2];
    const float* Why[2];
    const float* Whh[2];
    fp16*        WeffC[2];
    const float* bhh[2];
    const float* bxh[2];
    const float* bhy[2];
    float*       beff[2];
    const float* xs;
    fp16*        X;
    const float* Wraw[2];
    fp16*        Wbase;
};

__device__ void prep_weff(const PrepP& p, int id, int t)
{
    const int l  = id >> 6;
    const int rm = id & 63;
    const int m0 = (rm >> 3) * 64;
    const int n0 = (rm & 7) * 64;
    const float* __restrict__ A = p.Wxh[l];
    const float* __restrict__ B = p.Why[l];
    const float* __restrict__ Wadd = p.Whh[l];
    fp16* __restrict__ C = p.WeffC[l];

    __shared__ float As[16][64];
    __shared__ float Bs[16][64];
    const int tx = t & 15, ty = t >> 4;

    float acc[4][4] = {};
#pragma unroll 1
    for (int kt = 0; kt < 512; kt += 16) {
#pragma unroll
        for (int e = t; e < 1024; e += 256) {
            int am = e >> 4, ak = e & 15;
            As[ak][am] = A[(size_t)(m0 + am) * 512 + kt + ak];
            int bj = e & 63, bk = e >> 6;
            Bs[bk][bj] = B[(size_t)(kt + bk) * 512 + n0 + bj];
        }
        __syncthreads();
#pragma unroll
        for (int k = 0; k < 16; ++k) {
            float af[4], bf[4];
#pragma unroll
            for (int i = 0; i < 4; ++i) af[i] = As[k][ty * 4 + i];
#pragma unroll
            for (int j = 0; j < 4; ++j) bf[j] = Bs[k][tx * 4 + j];
#pragma unroll
            for (int i = 0; i < 4; ++i)
#pragma unroll
                for (int j = 0; j < 4; ++j)
                    acc[i][j] = fmaf(af[i], bf[j], acc[i][j]);
        }
        __syncthreads();
    }

    const int kcol = n0 + tx * 4;
#pragma unroll
    for (int i = 0; i < 4; ++i) {
        const int n = m0 + ty * 4 + i;
        fp16 h4[4];
#pragma unroll
        for (int j = 0; j < 4; ++j)
            h4[j] = __float2half_rn(Wadd[(size_t)n * 512 + kcol + j] + acc[i][j]);
        *(uint2*)(C + (size_t)n * 512 + kcol) = *(uint2*)h4;
    }
}

__device__ void prep_beff(const PrepP& p, int id, int t)
{
    const int gw = id * 8 + (t >> 5);
    const int l = gw >> 9;
    const int n = gw & 511;
    const int lane = t & 31;
    const float* W  = p.Wxh[l] + (size_t)n * 512 + lane * 16;
    const float* bh = p.bhy[l] + lane * 16;
    float s = 0.0f;
#pragma unroll
    for (int k = 0; k < 16; k += 4) {
        float4 w = *(const float4*)(W + k);
        float4 b = *(const float4*)(bh + k);
        s = fmaf(w.x, b.x, s); s = fmaf(w.y, b.y, s);
        s = fmaf(w.z, b.z, s); s = fmaf(w.w, b.w, s);
    }
#pragma unroll
    for (int o = 16; o; o >>= 1) s += __shfl_xor_sync(0xFFFFFFFFu, s, o);
    if (lane == 0) p.beff[l][n] = p.bhh[l][n] + p.bxh[l][n] + s;
}

// Coalesced fp32 -> fp16 conversion: block converts 8192 consecutive floats.
// Each iteration the warp reads 32 contiguous float4 (512 B) and writes
// 32 contiguous 8 B half4 — fully coalesced, MLP 8 per thread.
__device__ void prep_cvt(const float* __restrict__ src, fp16* __restrict__ d,
                         int t)
{
#pragma unroll
    for (int j = 0; j < 8; ++j) {
        const int o = j * 1024 + t * 4;
        float4 v = *(const float4*)(src + o);
        __half2 h0, h1;
        h0.x = __float2half_rn(v.x); h0.y = __float2half_rn(v.y);
        h1.x = __float2half_rn(v.z); h1.y = __float2half_rn(v.w);
        uint2 pk;
        pk.x = *(uint32_t*)&h0;
        pk.y = *(uint32_t*)&h1;
        *(uint2*)(d + o) = pk;
    }
}

__global__ void __launch_bounds__(256) k_prep(PrepP p)
{
    const int bid = blockIdx.x;
    const int t   = threadIdx.x;

    if (bid < 128) {
        prep_weff(p, bid, t);
    } else if (bid < 256) {
        prep_beff(p, bid - 128, t);
    } else if (bid < 2304) {
        const size_t base = (size_t)(bid - 256) * 8192;
        prep_cvt(p.xs + base, p.X + base, t);
    } else {
        const int b = bid - 2304;                  // 0..63
        const int slot = b >> 5;                   // 32 blocks per slot
        const size_t base = (size_t)(b & 31) * 8192;
        prep_cvt(p.Wraw[slot] + base,
                 p.Wbase + (size_t)(slot * 3) * WELEMS + base, t);
    }
}

// --------------------------------- launcher ---------------------------------
extern "C" void kernel_launch(void* const* d_in, const int* in_sizes, int n_in,
                              void* d_out, int out_size)
{
    const float* xs     = (const float*)d_in[0];
    const float* W_xh0  = (const float*)d_in[1];
    const float* b_xh0  = (const float*)d_in[2];
    const float* b_hh0  = (const float*)d_in[4];
    const float* W_hy0  = (const float*)d_in[5];
    const float* b_hy0  = (const float*)d_in[6];
    const float* W_xh_h = (const float*)d_in[7];
    const float* b_xh_h = (const float*)d_in[8];
    const float* W_hh_h = (const float*)d_in[9];
    const float* b_hh_h = (const float*)d_in[10];
    const float* W_hy_h = (const float*)d_in[11];
    const float* b_hy_h = (const float*)d_in[12];

    float* out = (float*)d_out;
    float* hs_final = out + (size_t)4096 * 8 * HD;

    fp16 *X, *H0, *H1, *Wb;
    float *beff;
    cudaGetSymbolAddress((void**)&X,   g_X);
    cudaGetSymbolAddress((void**)&H0,  g_H0);
    cudaGetSymbolAddress((void**)&H1,  g_H1);
    cudaGetSymbolAddress((void**)&Wb,  g_W);
    cudaGetSymbolAddress((void**)&beff, g_beff);

    cudaFuncSetAttribute(gemm_stage<true,  false, false>,
                         cudaFuncAttributeMaxDynamicSharedMemorySize, SMEMB);
    cudaFuncSetAttribute(gemm_stage<true,  true,  false>,
                         cudaFuncAttributeMaxDynamicSharedMemorySize, SMEMB);
    cudaFuncSetAttribute(gemm_stage<false, false, true >,
                         cudaFuncAttributeMaxDynamicSharedMemorySize, SMEMB);

#define WS(s) (Wb + (size_t)(s) * WELEMS)

    // ---- fused prep ----
    PrepP pp;
    pp.Wxh[0] = W_xh_h;      pp.Wxh[1] = W_xh_h + WSZ;
    pp.Why[0] = W_hy0;       pp.Why[1] = W_hy_h;
    pp.Whh[0] = W_hh_h;      pp.Whh[1] = W_hh_h + WSZ;
    pp.WeffC[0] = WS(1);     pp.WeffC[1] = WS(2);
    pp.bhh[0] = b_hh_h;      pp.bhh[1] = b_hh_h + HD;
    pp.bxh[0] = b_xh_h;      pp.bxh[1] = b_xh_h + HD;
    pp.bhy[0] = b_hy0;       pp.bhy[1] = b_hy_h;
    pp.beff[0] = beff;       pp.beff[1] = beff + HD;
    pp.xs = xs;
    pp.X  = X;
    pp.Wraw[0] = W_xh0;
    pp.Wraw[1] = W_hy_h + WSZ;
    pp.Wbase = Wb;
    k_prep<<<2368, 256>>>(pp);

    dim3 grid(HD / BN, MROWS / BM);   // (4, 256) = 1024 CTAs
    dim3 block(NTH);

    // 1) h0 = tanh(X @ W_xh0^T + b_xh0 + b_hh0)
    gemm_stage<true, false, false><<<grid, block, SMEMB>>>(
        X, WS(0), b_xh0, b_hh0, H0, nullptr, nullptr);
    // 2) h1 = tanh(h0 @ Weff0^T + beff0)
    gemm_stage<true, false, false><<<grid, block, SMEMB>>>(
        H0, WS(1), beff, nullptr, H1, nullptr, nullptr);
    // 3) h2 = tanh(h1 @ Weff1^T + beff1)  (+ hs_final)
    gemm_stage<true, true, false><<<grid, block, SMEMB>>>(
        H1, WS(2), beff + HD, nullptr, H0, nullptr, hs_final);
    // 4) outputs = (h2 @ W_hy_h[1]^T + b_hy_h[1]) -> [S, B, H] fp32
    gemm_stage<false, false, true><<<grid, block, SMEMB>>>(
        H0, WS(3), b_hy_h + HD, nullptr, nullptr, out, nullptr);
#undef WS
}